// round 6
// baseline (speedup 1.0000x reference)
#include <cuda_runtime.h>
#include <cstdint>

#define N_NODES_C  500000
#define N_EDGES_C  8000000
#define N_GRAPHS_C 1000

#define LOG2E_F 1.4426950408889634f
#define SALPHA_F 1.7580993408473766f          // scale*alpha
#define SLN2_F   0.7282895255054788f          // scale*ln(2)

// Scratch (no cudaMalloc allowed)
__device__ float d_eon[N_NODES_C];
__device__ float d_g[N_GRAPHS_C * 11];
__device__ __align__(16) float d_EW[96];      // folded edge-stage weights (exp2-space)

__device__ __forceinline__ float ex2(float y) {
    float r;
    asm("ex2.approx.f32 %0, %1;" : "=f"(r) : "f"(y));
    return r;
}
// selu from y = x*log2(e):  selu(x) = s*ln2*max(y,0) + s*a*(2^min(y,0) - 1)
__device__ __forceinline__ float selu_y(float y) {
    float e   = ex2(fminf(y, 0.0f));
    float lin = fmaxf(y, 0.0f);
    return fmaf(SALPHA_F, e, fmaf(SLN2_F, lin, -SALPHA_F));
}

// ---------------------------------------------------------------------------
__global__ void zero_scratch() {
    int i = blockIdx.x * blockDim.x + threadIdx.x;
    int stride = gridDim.x * blockDim.x;
    float4* p = reinterpret_cast<float4*>(d_eon);
    for (int k = i; k < N_NODES_C / 4; k += stride)
        p[k] = make_float4(0.f, 0.f, 0.f, 0.f);
    for (int k = i; k < N_GRAPHS_C * 11; k += stride)
        d_g[k] = 0.f;
}

// ---------------------------------------------------------------------------
// d_EW layout:
//   [0:20)  pn_w1*L       [20:30) pn_b1*L
//   [30:80) M*L (M = pn_w2 @ ue_w1[1:,:])   [80:85) d*L
//   [85:90) ue_w1[0,:]*L  [90:95) ue_w2     [95] ue_b2
// ---------------------------------------------------------------------------
__global__ void setup_kernel(const float* __restrict__ pn_w1, const float* __restrict__ pn_b1,
                             const float* __restrict__ pn_w2, const float* __restrict__ pn_b2,
                             const float* __restrict__ ue_w1, const float* __restrict__ ue_b1,
                             const float* __restrict__ ue_w2, const float* __restrict__ ue_b2) {
    int t = threadIdx.x;
    if (t < 20) d_EW[t] = pn_w1[t] * LOG2E_F;
    if (t < 10) d_EW[20 + t] = pn_b1[t] * LOG2E_F;
    if (t < 50) {
        int j = t / 5, k = t % 5;
        float m = 0.0f;
        for (int q = 0; q < 10; ++q)
            m += pn_w2[j * 10 + q] * ue_w1[(1 + q) * 5 + k];
        d_EW[30 + t] = m * LOG2E_F;
    }
    if (t < 5) {
        float dd = ue_b1[t];
        for (int q = 0; q < 10; ++q)
            dd += pn_b2[q] * ue_w1[(1 + q) * 5 + t];
        d_EW[80 + t] = dd * LOG2E_F;
        d_EW[85 + t] = ue_w1[t] * LOG2E_F;
        d_EW[90 + t] = ue_w2[t];
    }
    if (t == 0) d_EW[95] = ue_b2[0];
}

// ---------------------------------------------------------------------------
// Edge stage: 2 adjacent edges/thread, M matrix in shared (broadcast LDS),
// next-iteration gathers prefetched. 4 blocks/SM x 128 => 16 warps.
// Operates on PAIR indices [pstart, pend).
// ---------------------------------------------------------------------------
__global__ __launch_bounds__(128, 4) void edge_kernel(
        const float* __restrict__ nodes, const float* __restrict__ edges,
        const int* __restrict__ senders, const int* __restrict__ receivers,
        int pstart, int pend) {
    __shared__ __align__(16) float sM[10][8];   // M[j][0..4], padded row=32B

    int t = threadIdx.x;
    if (t < 50) sM[t / 5][t % 5] = d_EW[30 + t];

    float WA[10], WB[10], WC[10];
    float D[5], U[5], V[5], B2;
#pragma unroll
    for (int j = 0; j < 10; ++j) {
        WA[j] = __ldg(d_EW + j);
        WB[j] = __ldg(d_EW + 10 + j);
        WC[j] = __ldg(d_EW + 20 + j);
    }
#pragma unroll
    for (int q = 0; q < 5; ++q) {
        D[q] = __ldg(d_EW + 80 + q);
        U[q] = __ldg(d_EW + 85 + q);
        V[q] = __ldg(d_EW + 90 + q);
    }
    B2 = __ldg(d_EW + 95);
    __syncthreads();

    const int2*   r2p = (const int2*)receivers;
    const int2*   s2p = (const int2*)senders;
    const float2* e2p = (const float2*)edges;

    const int stride = gridDim.x * blockDim.x;
    int p = pstart + blockIdx.x * blockDim.x + threadIdx.x;
    if (p >= pend) return;

    // prologue gathers
    int2   rr = __ldg(r2p + p);
    int2   ss = __ldg(s2p + p);
    float2 ee = __ldg(e2p + p);
    float nr0 = __ldg(nodes + rr.x);
    float ns0 = __ldg(nodes + ss.x);
    float nr1 = __ldg(nodes + rr.y);
    float ns1 = __ldg(nodes + ss.y);

    while (true) {
        // ---- prefetch next pair (clamped, branchless) ----
        int pn = p + stride;
        bool more = pn < pend;
        int pc = more ? pn : p;
        int2   rr_n = __ldg(r2p + pc);
        int2   ss_n = __ldg(s2p + pc);
        float2 ee_n = __ldg(e2p + pc);
        float nr0_n = __ldg(nodes + rr_n.x);
        float ns0_n = __ldg(nodes + ss_n.x);
        float nr1_n = __ldg(nodes + rr_n.y);
        float ns1_n = __ldg(nodes + ss_n.y);

        // ---- compute current pair ----
        float c0[5], c1[5];
#pragma unroll
        for (int q = 0; q < 5; ++q) { c0[q] = D[q]; c1[q] = D[q]; }

#pragma unroll
        for (int j = 0; j < 10; ++j) {
            float y0 = fmaf(nr0, WA[j], fmaf(ns0, WB[j], WC[j]));
            float y1 = fmaf(nr1, WA[j], fmaf(ns1, WB[j], WC[j]));
            float h0 = selu_y(y0);
            float h1 = selu_y(y1);
            float4 m4 = *reinterpret_cast<const float4*>(&sM[j][0]);
            float  m4e = sM[j][4];
            c0[0] = fmaf(h0, m4.x, c0[0]);  c1[0] = fmaf(h1, m4.x, c1[0]);
            c0[1] = fmaf(h0, m4.y, c0[1]);  c1[1] = fmaf(h1, m4.y, c1[1]);
            c0[2] = fmaf(h0, m4.z, c0[2]);  c1[2] = fmaf(h1, m4.z, c1[2]);
            c0[3] = fmaf(h0, m4.w, c0[3]);  c1[3] = fmaf(h1, m4.w, c1[3]);
            c0[4] = fmaf(h0, m4e, c0[4]);   c1[4] = fmaf(h1, m4e, c1[4]);
        }

        float ev0 = ee.x, ev1 = ee.y;
#pragma unroll
        for (int it = 0; it < 3; ++it) {
            float a0 = B2, a1 = B2;
#pragma unroll
            for (int q = 0; q < 5; ++q) {
                float y0 = fmaf(ev0, U[q], c0[q]);
                float y1 = fmaf(ev1, U[q], c1[q]);
                a0 = fmaf(selu_y(y0), V[q], a0);
                a1 = fmaf(selu_y(y1), V[q], a1);
            }
            ev0 = a0; ev1 = a1;
        }
        atomicAdd(&d_eon[rr.x], ev0);
        atomicAdd(&d_eon[rr.y], ev1);

        if (!more) break;
        p = pn;
        rr = rr_n; ee = ee_n;
        nr0 = nr0_n; ns0 = ns0_n; nr1 = nr1_n; ns1 = ns1_n;
        (void)ss_n;
    }
}

// ---------------------------------------------------------------------------
// Node stage: pe MLP + 3 un iterations, warp-aggregated segment sum into d_g.
// ---------------------------------------------------------------------------
__global__ __launch_bounds__(256) void node_kernel(
        const float* __restrict__ nodes, const int* __restrict__ graph_ids,
        const float* __restrict__ pe_w1, const float* __restrict__ pe_b1,
        const float* __restrict__ pe_w2, const float* __restrict__ pe_b2,
        const float* __restrict__ un_w1, const float* __restrict__ un_b1,
        const float* __restrict__ un_w2, const float* __restrict__ un_b2) {
    float PW1[5], PB1[5], PW2[50], PB2[10];
    float UW1[55], UB1[5], UW2[5], UB2v;
#pragma unroll
    for (int i = 0; i < 5; ++i) {
        PW1[i] = __ldg(pe_w1 + i) * LOG2E_F;
        PB1[i] = __ldg(pe_b1 + i) * LOG2E_F;
        UB1[i] = __ldg(un_b1 + i) * LOG2E_F;
        UW2[i] = __ldg(un_w2 + i);
    }
#pragma unroll
    for (int i = 0; i < 50; ++i) PW2[i] = __ldg(pe_w2 + i);
#pragma unroll
    for (int i = 0; i < 10; ++i) PB2[i] = __ldg(pe_b2 + i);
#pragma unroll
    for (int i = 0; i < 55; ++i) UW1[i] = __ldg(un_w1 + i) * LOG2E_F;
    UB2v = __ldg(un_b2);

    int stride = gridDim.x * blockDim.x;
    for (int n = blockIdx.x * blockDim.x + threadIdx.x; n < N_NODES_C; n += stride) {
        float eon = d_eon[n];
        float v[11];
        float hid[5];
#pragma unroll
        for (int k = 0; k < 5; ++k) hid[k] = selu_y(fmaf(eon, PW1[k], PB1[k]));
#pragma unroll
        for (int j = 0; j < 10; ++j) {
            float acc = PB2[j];
#pragma unroll
            for (int k = 0; k < 5; ++k) acc = fmaf(hid[k], PW2[k * 10 + j], acc);
            v[1 + j] = acc;
        }
        float c[5];
#pragma unroll
        for (int k = 0; k < 5; ++k) {
            float acc = UB1[k];
#pragma unroll
            for (int t = 0; t < 10; ++t) acc = fmaf(v[1 + t], UW1[(1 + t) * 5 + k], acc);
            c[k] = acc;
        }
        float x = nodes[n];
#pragma unroll
        for (int it = 0; it < 3; ++it) {
            float acc = UB2v;
#pragma unroll
            for (int k = 0; k < 5; ++k)
                acc = fmaf(selu_y(fmaf(x, UW1[k], c[k])), UW2[k], acc);
            x = acc;
        }
        v[0] = x;

        int gid = graph_ids[n];
        const unsigned mask = 0xffffffffu;
        int g0 = __shfl_sync(mask, gid, 0);
        bool uni = __all_sync(mask, gid == g0);
        if (uni) {
#pragma unroll
            for (int j = 0; j < 11; ++j) {
                float vv = v[j];
#pragma unroll
                for (int off = 16; off > 0; off >>= 1)
                    vv += __shfl_down_sync(mask, vv, off);
                if ((threadIdx.x & 31) == 0) atomicAdd(&d_g[g0 * 11 + j], vv);
            }
        } else {
#pragma unroll
            for (int j = 0; j < 11; ++j)
                atomicAdd(&d_g[gid * 11 + j], v[j]);
        }
    }
}

// ---------------------------------------------------------------------------
__global__ void graph_kernel(const float* __restrict__ pr_w1, const float* __restrict__ pr_b1,
                             const float* __restrict__ pr_w2, const float* __restrict__ pr_b2,
                             float* __restrict__ out) {
    int g = blockIdx.x * blockDim.x + threadIdx.x;
    if (g >= N_GRAPHS_C) return;
    float gv[11];
#pragma unroll
    for (int i = 0; i < 11; ++i) gv[i] = d_g[g * 11 + i];
    float hid[10];
#pragma unroll
    for (int j = 0; j < 10; ++j) {
        float acc = __ldg(pr_b1 + j) * LOG2E_F;
#pragma unroll
        for (int i = 0; i < 11; ++i)
            acc = fmaf(gv[i], __ldg(pr_w1 + i * 10 + j) * LOG2E_F, acc);
        hid[j] = selu_y(acc);
    }
    float o[10];
    float mx = -1e30f;
#pragma unroll
    for (int k = 0; k < 10; ++k) {
        float acc = __ldg(pr_b2 + k) * LOG2E_F;
#pragma unroll
        for (int j = 0; j < 10; ++j)
            acc = fmaf(hid[j], __ldg(pr_w2 + j * 10 + k) * LOG2E_F, acc);
        o[k] = acc;
        mx = fmaxf(mx, acc);
    }
    float sum = 0.0f;
#pragma unroll
    for (int k = 0; k < 10; ++k) { o[k] = ex2(o[k] - mx); sum += o[k]; }
    float inv = 1.0f / sum;
#pragma unroll
    for (int k = 0; k < 10; ++k) out[g * 10 + k] = o[k] * inv;
}

// ---------------------------------------------------------------------------
extern "C" void kernel_launch(void* const* d_in, const int* in_sizes, int n_in,
                              void* d_out, int out_size) {
    const float* nodes = (const float*)d_in[0];
    const float* edges = (const float*)d_in[1];
    const int *senders, *receivers, *graph_ids;
    const float* w[20];

    if (in_sizes[2] == N_EDGES_C) {
        senders   = (const int*)d_in[2];
        receivers = (const int*)d_in[3];
        graph_ids = (const int*)d_in[4];
        int base = (n_in > 25 && in_sizes[5] == 1) ? 6 : 5;
        for (int i = 0; i < 20; ++i) w[i] = (const float*)d_in[base + i];
    } else {
        for (int i = 0; i < 20; ++i) w[i] = (const float*)d_in[2 + i];
        senders   = (const int*)d_in[22];
        receivers = (const int*)d_in[23];
        graph_ids = (const int*)d_in[24];
    }

    // idx 0 zero, 1 setup, 2..5 edge chunks, 6 node, 7 graph.
    zero_scratch<<<232, 256>>>();
    setup_kernel<<<1, 64>>>(w[0], w[1], w[2], w[3], w[4], w[5], w[6], w[7]);

    const int NP = N_EDGES_C / 2;      // pair count
    const int NCHUNK = 4;
    int chunk = (NP + NCHUNK - 1) / NCHUNK;
    for (int i = 0; i < NCHUNK; ++i) {
        int s = i * chunk;
        int e = s + chunk; if (e > NP) e = NP;
        edge_kernel<<<592, 128>>>(nodes, edges, senders, receivers, s, e);
    }
    node_kernel<<<148, 256>>>(nodes, graph_ids,
                              w[8], w[9], w[10], w[11],
                              w[12], w[13], w[14], w[15]);
    graph_kernel<<<32, 32>>>(w[16], w[17], w[18], w[19], (float*)d_out);
}

// round 7
// speedup vs baseline: 1.0521x; 1.0521x over previous
#include <cuda_runtime.h>
#include <cstdint>

#define N_NODES_C  500000
#define N_EDGES_C  8000000
#define N_GRAPHS_C 1000

#define LOG2E_F 1.4426950408889634f
#define SALPHA_F 1.7580993408473766f          // scale*alpha
#define SLN2_F   0.7282895255054788f          // scale*ln(2)

// Scratch (no cudaMalloc allowed)
__device__ float d_eon[N_NODES_C];
__device__ float d_g[N_GRAPHS_C * 11];
__device__ __align__(16) float d_EW[96];      // folded edge-stage weights (exp2-space)

__device__ __forceinline__ float ex2(float y) {
    float r;
    asm("ex2.approx.f32 %0, %1;" : "=f"(r) : "f"(y));
    return r;
}
// selu from y = x*log2(e):  selu(x) = s*ln2*max(y,0) + s*a*(2^min(y,0) - 1)
__device__ __forceinline__ float selu_y(float y) {
    float e   = ex2(fminf(y, 0.0f));
    float lin = fmaxf(y, 0.0f);
    return fmaf(SALPHA_F, e, fmaf(SLN2_F, lin, -SALPHA_F));
}

// ---------------------------------------------------------------------------
__global__ void zero_scratch() {
    int i = blockIdx.x * blockDim.x + threadIdx.x;
    int stride = gridDim.x * blockDim.x;
    float4* p = reinterpret_cast<float4*>(d_eon);
    for (int k = i; k < N_NODES_C / 4; k += stride)
        p[k] = make_float4(0.f, 0.f, 0.f, 0.f);
    for (int k = i; k < N_GRAPHS_C * 11; k += stride)
        d_g[k] = 0.f;
}

// ---------------------------------------------------------------------------
// d_EW layout:
//   [0:20)  pn_w1*L       [20:30) pn_b1*L
//   [30:80) M*L (M = pn_w2 @ ue_w1[1:,:])   [80:85) d*L
//   [85:90) ue_w1[0,:]*L  [90:95) ue_w2     [95] ue_b2
// ---------------------------------------------------------------------------
__global__ void setup_kernel(const float* __restrict__ pn_w1, const float* __restrict__ pn_b1,
                             const float* __restrict__ pn_w2, const float* __restrict__ pn_b2,
                             const float* __restrict__ ue_w1, const float* __restrict__ ue_b1,
                             const float* __restrict__ ue_w2, const float* __restrict__ ue_b2) {
    int t = threadIdx.x;
    if (t < 20) d_EW[t] = pn_w1[t] * LOG2E_F;
    if (t < 10) d_EW[20 + t] = pn_b1[t] * LOG2E_F;
    if (t < 50) {
        int j = t / 5, k = t % 5;
        float m = 0.0f;
        for (int q = 0; q < 10; ++q)
            m += pn_w2[j * 10 + q] * ue_w1[(1 + q) * 5 + k];
        d_EW[30 + t] = m * LOG2E_F;
    }
    if (t < 5) {
        float dd = ue_b1[t];
        for (int q = 0; q < 10; ++q)
            dd += pn_b2[q] * ue_w1[(1 + q) * 5 + t];
        d_EW[80 + t] = dd * LOG2E_F;
        d_EW[85 + t] = ue_w1[t] * LOG2E_F;
        d_EW[90 + t] = ue_w2[t];
    }
    if (t == 0) d_EW[95] = ue_b2[0];
}

// ---------------------------------------------------------------------------
// Edge stage: 4 adjacent edges/thread (int4/float4 loads), 8 random gathers
// in flight before compute, M matrix in shared (broadcast LDS).
// 4 blocks/SM x 128 => 16 warps, reg cap 128, no spill (M not in regs).
// Operates on QUAD indices [qstart, qend).
// ---------------------------------------------------------------------------
__global__ __launch_bounds__(128, 4) void edge_kernel(
        const float* __restrict__ nodes, const float* __restrict__ edges,
        const int* __restrict__ senders, const int* __restrict__ receivers,
        int qstart, int qend) {
    __shared__ __align__(16) float sM[10][8];   // M[j][0..4], padded row=32B

    int t = threadIdx.x;
    if (t < 50) sM[t / 5][t % 5] = d_EW[30 + t];

    float WA[10], WB[10], WC[10];
    float D[5], U[5], V[5], B2;
#pragma unroll
    for (int j = 0; j < 10; ++j) {
        WA[j] = __ldg(d_EW + j);
        WB[j] = __ldg(d_EW + 10 + j);
        WC[j] = __ldg(d_EW + 20 + j);
    }
#pragma unroll
    for (int q = 0; q < 5; ++q) {
        D[q] = __ldg(d_EW + 80 + q);
        U[q] = __ldg(d_EW + 85 + q);
        V[q] = __ldg(d_EW + 90 + q);
    }
    B2 = __ldg(d_EW + 95);
    __syncthreads();

    const int4*   r4p = (const int4*)receivers;
    const int4*   s4p = (const int4*)senders;
    const float4* e4p = (const float4*)edges;

    const int stride = gridDim.x * blockDim.x;
    for (int q = qstart + blockIdx.x * blockDim.x + threadIdx.x; q < qend; q += stride) {
        int4   rr = __ldg(r4p + q);
        int4   ss = __ldg(s4p + q);
        float4 ee = __ldg(e4p + q);

        // all 8 random gathers in flight before any compute
        float nr0 = __ldg(nodes + rr.x);
        float ns0 = __ldg(nodes + ss.x);
        float nr1 = __ldg(nodes + rr.y);
        float ns1 = __ldg(nodes + ss.y);
        float nr2 = __ldg(nodes + rr.z);
        float ns2 = __ldg(nodes + ss.z);
        float nr3 = __ldg(nodes + rr.w);
        float ns3 = __ldg(nodes + ss.w);

        float c0[5], c1[5], c2[5], c3[5];
#pragma unroll
        for (int k = 0; k < 5; ++k) { c0[k] = D[k]; c1[k] = D[k]; c2[k] = D[k]; c3[k] = D[k]; }

#pragma unroll
        for (int j = 0; j < 10; ++j) {
            float h0 = selu_y(fmaf(nr0, WA[j], fmaf(ns0, WB[j], WC[j])));
            float h1 = selu_y(fmaf(nr1, WA[j], fmaf(ns1, WB[j], WC[j])));
            float h2 = selu_y(fmaf(nr2, WA[j], fmaf(ns2, WB[j], WC[j])));
            float h3 = selu_y(fmaf(nr3, WA[j], fmaf(ns3, WB[j], WC[j])));
            float4 m4 = *reinterpret_cast<const float4*>(&sM[j][0]);
            float  m4e = sM[j][4];
            c0[0] = fmaf(h0, m4.x, c0[0]); c1[0] = fmaf(h1, m4.x, c1[0]);
            c2[0] = fmaf(h2, m4.x, c2[0]); c3[0] = fmaf(h3, m4.x, c3[0]);
            c0[1] = fmaf(h0, m4.y, c0[1]); c1[1] = fmaf(h1, m4.y, c1[1]);
            c2[1] = fmaf(h2, m4.y, c2[1]); c3[1] = fmaf(h3, m4.y, c3[1]);
            c0[2] = fmaf(h0, m4.z, c0[2]); c1[2] = fmaf(h1, m4.z, c1[2]);
            c2[2] = fmaf(h2, m4.z, c2[2]); c3[2] = fmaf(h3, m4.z, c3[2]);
            c0[3] = fmaf(h0, m4.w, c0[3]); c1[3] = fmaf(h1, m4.w, c1[3]);
            c2[3] = fmaf(h2, m4.w, c2[3]); c3[3] = fmaf(h3, m4.w, c3[3]);
            c0[4] = fmaf(h0, m4e, c0[4]);  c1[4] = fmaf(h1, m4e, c1[4]);
            c2[4] = fmaf(h2, m4e, c2[4]);  c3[4] = fmaf(h3, m4e, c3[4]);
        }

        float ev0 = ee.x, ev1 = ee.y, ev2 = ee.z, ev3 = ee.w;
#pragma unroll
        for (int it = 0; it < 3; ++it) {
            float a0 = B2, a1 = B2, a2 = B2, a3 = B2;
#pragma unroll
            for (int k = 0; k < 5; ++k) {
                a0 = fmaf(selu_y(fmaf(ev0, U[k], c0[k])), V[k], a0);
                a1 = fmaf(selu_y(fmaf(ev1, U[k], c1[k])), V[k], a1);
                a2 = fmaf(selu_y(fmaf(ev2, U[k], c2[k])), V[k], a2);
                a3 = fmaf(selu_y(fmaf(ev3, U[k], c3[k])), V[k], a3);
            }
            ev0 = a0; ev1 = a1; ev2 = a2; ev3 = a3;
        }
        atomicAdd(&d_eon[rr.x], ev0);
        atomicAdd(&d_eon[rr.y], ev1);
        atomicAdd(&d_eon[rr.z], ev2);
        atomicAdd(&d_eon[rr.w], ev3);
    }
}

// ---------------------------------------------------------------------------
// Node stage: pe MLP + 3 un iterations, warp-aggregated segment sum into d_g.
// ---------------------------------------------------------------------------
__global__ __launch_bounds__(256) void node_kernel(
        const float* __restrict__ nodes, const int* __restrict__ graph_ids,
        const float* __restrict__ pe_w1, const float* __restrict__ pe_b1,
        const float* __restrict__ pe_w2, const float* __restrict__ pe_b2,
        const float* __restrict__ un_w1, const float* __restrict__ un_b1,
        const float* __restrict__ un_w2, const float* __restrict__ un_b2) {
    float PW1[5], PB1[5], PW2[50], PB2[10];
    float UW1[55], UB1[5], UW2[5], UB2v;
#pragma unroll
    for (int i = 0; i < 5; ++i) {
        PW1[i] = __ldg(pe_w1 + i) * LOG2E_F;
        PB1[i] = __ldg(pe_b1 + i) * LOG2E_F;
        UB1[i] = __ldg(un_b1 + i) * LOG2E_F;
        UW2[i] = __ldg(un_w2 + i);
    }
#pragma unroll
    for (int i = 0; i < 50; ++i) PW2[i] = __ldg(pe_w2 + i);
#pragma unroll
    for (int i = 0; i < 10; ++i) PB2[i] = __ldg(pe_b2 + i);
#pragma unroll
    for (int i = 0; i < 55; ++i) UW1[i] = __ldg(un_w1 + i) * LOG2E_F;
    UB2v = __ldg(un_b2);

    int stride = gridDim.x * blockDim.x;
    for (int n = blockIdx.x * blockDim.x + threadIdx.x; n < N_NODES_C; n += stride) {
        float eon = d_eon[n];
        float v[11];
        float hid[5];
#pragma unroll
        for (int k = 0; k < 5; ++k) hid[k] = selu_y(fmaf(eon, PW1[k], PB1[k]));
#pragma unroll
        for (int j = 0; j < 10; ++j) {
            float acc = PB2[j];
#pragma unroll
            for (int k = 0; k < 5; ++k) acc = fmaf(hid[k], PW2[k * 10 + j], acc);
            v[1 + j] = acc;
        }
        float c[5];
#pragma unroll
        for (int k = 0; k < 5; ++k) {
            float acc = UB1[k];
#pragma unroll
            for (int t = 0; t < 10; ++t) acc = fmaf(v[1 + t], UW1[(1 + t) * 5 + k], acc);
            c[k] = acc;
        }
        float x = nodes[n];
#pragma unroll
        for (int it = 0; it < 3; ++it) {
            float acc = UB2v;
#pragma unroll
            for (int k = 0; k < 5; ++k)
                acc = fmaf(selu_y(fmaf(x, UW1[k], c[k])), UW2[k], acc);
            x = acc;
        }
        v[0] = x;

        int gid = graph_ids[n];
        const unsigned mask = 0xffffffffu;
        int g0 = __shfl_sync(mask, gid, 0);
        bool uni = __all_sync(mask, gid == g0);
        if (uni) {
#pragma unroll
            for (int j = 0; j < 11; ++j) {
                float vv = v[j];
#pragma unroll
                for (int off = 16; off > 0; off >>= 1)
                    vv += __shfl_down_sync(mask, vv, off);
                if ((threadIdx.x & 31) == 0) atomicAdd(&d_g[g0 * 11 + j], vv);
            }
        } else {
#pragma unroll
            for (int j = 0; j < 11; ++j)
                atomicAdd(&d_g[gid * 11 + j], v[j]);
        }
    }
}

// ---------------------------------------------------------------------------
__global__ void graph_kernel(const float* __restrict__ pr_w1, const float* __restrict__ pr_b1,
                             const float* __restrict__ pr_w2, const float* __restrict__ pr_b2,
                             float* __restrict__ out) {
    int g = blockIdx.x * blockDim.x + threadIdx.x;
    if (g >= N_GRAPHS_C) return;
    float gv[11];
#pragma unroll
    for (int i = 0; i < 11; ++i) gv[i] = d_g[g * 11 + i];
    float hid[10];
#pragma unroll
    for (int j = 0; j < 10; ++j) {
        float acc = __ldg(pr_b1 + j) * LOG2E_F;
#pragma unroll
        for (int i = 0; i < 11; ++i)
            acc = fmaf(gv[i], __ldg(pr_w1 + i * 10 + j) * LOG2E_F, acc);
        hid[j] = selu_y(acc);
    }
    float o[10];
    float mx = -1e30f;
#pragma unroll
    for (int k = 0; k < 10; ++k) {
        float acc = __ldg(pr_b2 + k) * LOG2E_F;
#pragma unroll
        for (int j = 0; j < 10; ++j)
            acc = fmaf(hid[j], __ldg(pr_w2 + j * 10 + k) * LOG2E_F, acc);
        o[k] = acc;
        mx = fmaxf(mx, acc);
    }
    float sum = 0.0f;
#pragma unroll
    for (int k = 0; k < 10; ++k) { o[k] = ex2(o[k] - mx); sum += o[k]; }
    float inv = 1.0f / sum;
#pragma unroll
    for (int k = 0; k < 10; ++k) out[g * 10 + k] = o[k] * inv;
}

// ---------------------------------------------------------------------------
extern "C" void kernel_launch(void* const* d_in, const int* in_sizes, int n_in,
                              void* d_out, int out_size) {
    const float* nodes = (const float*)d_in[0];
    const float* edges = (const float*)d_in[1];
    const int *senders, *receivers, *graph_ids;
    const float* w[20];

    if (in_sizes[2] == N_EDGES_C) {
        senders   = (const int*)d_in[2];
        receivers = (const int*)d_in[3];
        graph_ids = (const int*)d_in[4];
        int base = (n_in > 25 && in_sizes[5] == 1) ? 6 : 5;
        for (int i = 0; i < 20; ++i) w[i] = (const float*)d_in[base + i];
    } else {
        for (int i = 0; i < 20; ++i) w[i] = (const float*)d_in[2 + i];
        senders   = (const int*)d_in[22];
        receivers = (const int*)d_in[23];
        graph_ids = (const int*)d_in[24];
    }

    // idx 0 zero, 1 setup, 2..5 edge chunks, 6 node, 7 graph.
    zero_scratch<<<232, 256>>>();
    setup_kernel<<<1, 64>>>(w[0], w[1], w[2], w[3], w[4], w[5], w[6], w[7]);

    const int NQ = N_EDGES_C / 4;      // quad count (8M % 4 == 0)
    const int NCHUNK = 4;
    int chunk = (NQ + NCHUNK - 1) / NCHUNK;
    for (int i = 0; i < NCHUNK; ++i) {
        int s = i * chunk;
        int e = s + chunk; if (e > NQ) e = NQ;
        edge_kernel<<<592, 128>>>(nodes, edges, senders, receivers, s, e);
    }
    node_kernel<<<148, 256>>>(nodes, graph_ids,
                              w[8], w[9], w[10], w[11],
                              w[12], w[13], w[14], w[15]);
    graph_kernel<<<32, 32>>>(w[16], w[17], w[18], w[19], (float*)d_out);
}